// round 15
// baseline (speedup 1.0000x reference)
#include <cuda_runtime.h>
#include <cuda_fp16.h>
#include <cstdint>
#include <cstddef>

// ---------------------------------------------------------------------------
// Problem constants
// ---------------------------------------------------------------------------
#define NF 100000
#define NE 200000
#define HID 128
#define RAW 512
#define NEDGE 1000000

// ---------------------------------------------------------------------------
// Scratch (device globals -- no allocation allowed)
// ---------------------------------------------------------------------------
__device__ __half g_x_fr16[(size_t)NF * HID];
__device__ __half g_x_fe16[(size_t)NE * HID];
__device__ __half g_h_fr16[(size_t)NF * HID];
__device__ __half g_h_fe16[(size_t)NE * HID];
__device__ __half g_h2_fr16[(size_t)NF * HID];
__device__ __half g_h2_fe16[(size_t)NE * HID];
__device__ __half g_aggF[(size_t)NF * 256];
__device__ __half g_aggE[(size_t)NE * 256];
__device__ int    g_ideg[(size_t)4 * NF + (size_t)4 * NE];
__device__ float  g_deg[(size_t)4 * NF + (size_t)4 * NE];
__device__ __half g_WlinF_t[(size_t)HID * RAW];
__device__ __half g_WlinE_t[(size_t)HID * RAW];
__device__ __half g_WcatF_t[(size_t)HID * 256];
__device__ __half g_WcatE_t[(size_t)HID * 256];
__device__ __half g_WfcF_t[(size_t)RAW * HID];
__device__ __half g_WfcE_t[(size_t)RAW * HID];
__device__ float  g_bias_gF[HID];
__device__ float  g_bias_gE[HID];
__device__ int g_csr_ff[NEDGE];
__device__ int g_csr_ef[NEDGE];
__device__ int g_csr_fE[NEDGE];
__device__ int g_csr_ee[NEDGE];
__device__ float g_wcsr_ff[NEDGE];
__device__ float g_wcsr_ef[NEDGE];
__device__ float g_wcsr_fE[NEDGE];
__device__ float g_wcsr_ee[NEDGE];
__device__ int g_row_ff[NF];  __device__ int g_cur_ff[NF];
__device__ int g_row_ef[NF];  __device__ int g_cur_ef[NF];
__device__ int g_row_fE[NE];  __device__ int g_cur_fE[NE];
__device__ int g_row_ee[NE];  __device__ int g_cur_ee[NE];
__device__ int g_part[(size_t)4 * NE];
__device__ int g_bsum[4 * 1024];

// ---------------------------------------------------------------------------
// Helpers
// ---------------------------------------------------------------------------
__device__ __forceinline__ uint32_t smem_u32(const void* p) {
    uint32_t r;
    asm("{ .reg .u64 t; cvta.to.shared.u64 t, %1; cvt.u32.u64 %0, t; }"
        : "=r"(r) : "l"(p));
    return r;
}

__device__ __forceinline__ uint32_t packh2(float x, float y) {
    __half2 h = __floats2half2_rn(x, y);
    return *(uint32_t*)&h;
}

// ---------------------------------------------------------------------------
// Consolidated prep kernels
// ---------------------------------------------------------------------------
__global__ void zero_kernel(float* __restrict__ p, size_t n4) {
    size_t i = (size_t)blockIdx.x * blockDim.x + threadIdx.x;
    if (i < n4) ((float4*)p)[i] = make_float4(0.f, 0.f, 0.f, 0.f);
}

__global__ void wprep_kernel(
    const float* __restrict__ WlinF, const float* __restrict__ WlinE,
    const float* __restrict__ W_frfr, const float* __restrict__ W_fefr,
    const float* __restrict__ W_frfe, const float* __restrict__ W_fefe,
    const float* __restrict__ WfcF, const float* __restrict__ WfcE,
    const float* __restrict__ b_frfr, const float* __restrict__ b_fefr,
    const float* __restrict__ b_frfe, const float* __restrict__ b_fefe,
    __half* __restrict__ oLinF, __half* __restrict__ oLinE,
    __half* __restrict__ oCatF, __half* __restrict__ oCatE,
    __half* __restrict__ oFcF, __half* __restrict__ oFcE,
    float* __restrict__ obF, float* __restrict__ obE) {
    int idx = blockIdx.x * blockDim.x + threadIdx.x;
    if (idx < 65536) {                                    // WlinX_t [128][512]
        int n = idx >> 9, k = idx & 511;
        oLinF[idx] = __float2half(WlinF[(size_t)k * HID + n]);
        oLinE[idx] = __float2half(WlinE[(size_t)k * HID + n]);
        return;
    }
    idx -= 65536;
    if (idx < 32768) {                                    // Wcat [128][256]
        int n = idx >> 8, k = idx & 255;
        float vF = (k < 128) ? W_frfr[(size_t)k * 128 + n]
                             : W_fefr[(size_t)(k - 128) * 128 + n];
        float vE = (k < 128) ? W_frfe[(size_t)k * 128 + n]
                             : W_fefe[(size_t)(k - 128) * 128 + n];
        oCatF[idx] = __float2half(vF);
        oCatE[idx] = __float2half(vE);
        return;
    }
    idx -= 32768;
    if (idx < 65536) {                                    // Wfc_t [512][128]
        int n = idx >> 7, k = idx & 127;
        oFcF[idx] = __float2half(WfcF[(size_t)k * RAW + n]);
        oFcE[idx] = __float2half(WfcE[(size_t)k * RAW + n]);
        return;
    }
    idx -= 65536;
    if (idx < 128) {
        obF[idx] = 0.5f * (b_frfr[idx] + b_fefr[idx]);
        obE[idx] = 0.5f * (b_frfe[idx] + b_fefe[idx]);
    }
}

__global__ void deg_all_kernel(
    const int* __restrict__ s0, const int* __restrict__ d0,
    const int* __restrict__ s1, const int* __restrict__ d1,
    const int* __restrict__ s2, const int* __restrict__ d2,
    const int* __restrict__ s3, const int* __restrict__ d3,
    int* __restrict__ o0, int* __restrict__ i0,
    int* __restrict__ o1, int* __restrict__ i1,
    int* __restrict__ o2, int* __restrict__ i2,
    int* __restrict__ o3, int* __restrict__ i3, int n) {
    int i = blockIdx.x * blockDim.x + threadIdx.x;
    if (i >= n) return;
    switch (blockIdx.y) {
        case 0: atomicAdd(&o0[s0[i]], 1); atomicAdd(&i0[d0[i]], 1); break;
        case 1: atomicAdd(&o1[s1[i]], 1); atomicAdd(&i1[d1[i]], 1); break;
        case 2: atomicAdd(&o2[s2[i]], 1); atomicAdd(&i2[d2[i]], 1); break;
        default: atomicAdd(&o3[s3[i]], 1); atomicAdd(&i3[d3[i]], 1); break;
    }
}

__global__ void norm_kernel(const int* __restrict__ d, float* __restrict__ p, int n) {
    int i = blockIdx.x * blockDim.x + threadIdx.x;
    if (i < n) {
        int v = d[i];
        p[i] = (v > 0) ? rsqrtf((float)v) : 0.f;
    }
}

// ---------------------------------------------------------------------------
// Batched CSR build: 4 relations per launch (grid.y = relation)
// ---------------------------------------------------------------------------
__global__ void scan_partial4(
    const int* __restrict__ in0, const int* __restrict__ in1,
    const int* __restrict__ in2, const int* __restrict__ in3,
    int* __restrict__ part, int* __restrict__ bsum,
    int n0, int n1, int n2, int n3) {
    int rel = blockIdx.y;
    const int* in = rel == 0 ? in0 : rel == 1 ? in1 : rel == 2 ? in2 : in3;
    int n = rel == 0 ? n0 : rel == 1 ? n1 : rel == 2 ? n2 : n3;
    if (blockIdx.x * 256 >= n) return;
    __shared__ int sh[256];
    int t = threadIdx.x;
    int i = blockIdx.x * 256 + t;
    int v = (i < n) ? in[i] : 0;
    sh[t] = v;
    __syncthreads();
#pragma unroll
    for (int off = 1; off < 256; off <<= 1) {
        int u = (t >= off) ? sh[t - off] : 0;
        __syncthreads();
        sh[t] += u;
        __syncthreads();
    }
    if (i < n) part[(size_t)rel * NE + i] = sh[t] - v;
    if (t == 255) bsum[rel * 1024 + blockIdx.x] = sh[255];
}

__global__ void scan_bsum4(int* __restrict__ bsum, int nb0, int nb1, int nb2, int nb3) {
    int rel = blockIdx.x;
    int nb = rel == 0 ? nb0 : rel == 1 ? nb1 : rel == 2 ? nb2 : nb3;
    int* bs = bsum + rel * 1024;
    __shared__ int sh[1024];
    int t = threadIdx.x;
    int v = (t < nb) ? bs[t] : 0;
    sh[t] = v;
    __syncthreads();
#pragma unroll
    for (int off = 1; off < 1024; off <<= 1) {
        int u = (t >= off) ? sh[t - off] : 0;
        __syncthreads();
        sh[t] += u;
        __syncthreads();
    }
    if (t < nb) bs[t] = sh[t] - v;
}

__global__ void scan_add4(
    const int* __restrict__ part, const int* __restrict__ bsum,
    int* __restrict__ row0, int* __restrict__ cur0,
    int* __restrict__ row1, int* __restrict__ cur1,
    int* __restrict__ row2, int* __restrict__ cur2,
    int* __restrict__ row3, int* __restrict__ cur3,
    int n0, int n1, int n2, int n3) {
    int rel = blockIdx.y;
    int n = rel == 0 ? n0 : rel == 1 ? n1 : rel == 2 ? n2 : n3;
    int i = blockIdx.x * 256 + threadIdx.x;
    if (i >= n) return;
    int v = part[(size_t)rel * NE + i] + bsum[rel * 1024 + blockIdx.x];
    switch (rel) {
        case 0: row0[i] = v; cur0[i] = v; break;
        case 1: row1[i] = v; cur1[i] = v; break;
        case 2: row2[i] = v; cur2[i] = v; break;
        default: row3[i] = v; cur3[i] = v; break;
    }
}

// fill CSR src index AND per-edge source-norm weight (cuts the ns[sidx]
// pointer-chase out of the gather's critical path)
__global__ void fill4(
    const int* __restrict__ s0, const int* __restrict__ d0,
    const int* __restrict__ s1, const int* __restrict__ d1,
    const int* __restrict__ s2, const int* __restrict__ d2,
    const int* __restrict__ s3, const int* __restrict__ d3,
    const float* __restrict__ ns0, const float* __restrict__ ns1,
    const float* __restrict__ ns2, const float* __restrict__ ns3,
    int* __restrict__ c0, int* __restrict__ r0, float* __restrict__ w0,
    int* __restrict__ c1, int* __restrict__ r1, float* __restrict__ w1,
    int* __restrict__ c2, int* __restrict__ r2, float* __restrict__ w2,
    int* __restrict__ c3, int* __restrict__ r3, float* __restrict__ w3,
    int n) {
    int i = blockIdx.x * blockDim.x + threadIdx.x;
    if (i >= n) return;
    int s, pos;
    switch (blockIdx.y) {
        case 0:
            s = s0[i]; pos = atomicAdd(&c0[d0[i]], 1);
            r0[pos] = s; w0[pos] = ns0[s]; break;
        case 1:
            s = s1[i]; pos = atomicAdd(&c1[d1[i]], 1);
            r1[pos] = s; w1[pos] = ns1[s]; break;
        case 2:
            s = s2[i]; pos = atomicAdd(&c2[d2[i]], 1);
            r2[pos] = s; w2[pos] = ns2[s]; break;
        default:
            s = s3[i]; pos = atomicAdd(&c3[d3[i]], 1);
            r3[pos] = s; w3[pos] = ns3[s]; break;
    }
}

// ---------------------------------------------------------------------------
// Gather aggregation over a node range [base, base+count):
// node id < NF -> F-dst (rels ff, ef) -> aggF.  else -> E-dst -> aggE.
// Per-edge weight pre-materialized (wcsr) -> no dependent ns lookup.
// ---------------------------------------------------------------------------
__device__ __forceinline__ void gather_rel(const __half* __restrict__ x,
                                           const int* __restrict__ csr,
                                           const float* __restrict__ wcsr,
                                           int start, int dc,
                                           int lane, float4& a) {
    for (int base = 0; base < dc; base += 32) {
        int e = base + lane;
        int sidx = 0; float wv = 0.f;
        if (e < dc) { sidx = csr[start + e]; wv = wcsr[start + e]; }
        int m = min(32, dc - base);
        for (int j = 0; j < m; j++) {
            int s = __shfl_sync(0xffffffffu, sidx, j);
            float w = __shfl_sync(0xffffffffu, wv, j);
            uint2 raw = __ldg(&((const uint2*)(x + (size_t)s * HID))[lane]);
            float2 f0 = __half22float2(*(__half2*)&raw.x);
            float2 f1 = __half22float2(*(__half2*)&raw.y);
            a.x += f0.x * w; a.y += f0.y * w;
            a.z += f1.x * w; a.w += f1.y * w;
        }
    }
}

__global__ void __launch_bounds__(256)
gather_all(const __half* __restrict__ xF, const __half* __restrict__ xE,
           const int* __restrict__ csr_ff, const float* __restrict__ w_ff,
           const int* __restrict__ row_ff, const int* __restrict__ din_ff,
           const float* __restrict__ nd_ff,
           const int* __restrict__ csr_ef, const float* __restrict__ w_ef,
           const int* __restrict__ row_ef, const int* __restrict__ din_ef,
           const float* __restrict__ nd_ef,
           const int* __restrict__ csr_fE, const float* __restrict__ w_fE,
           const int* __restrict__ row_fE, const int* __restrict__ din_fE,
           const float* __restrict__ nd_fE,
           const int* __restrict__ csr_ee, const float* __restrict__ w_ee,
           const int* __restrict__ row_ee, const int* __restrict__ din_ee,
           const float* __restrict__ nd_ee,
           __half* __restrict__ aggF, __half* __restrict__ aggE,
           int base_node, int count) {
    int wi = (blockIdx.x * blockDim.x + threadIdx.x) >> 5;
    if (wi >= count) return;
    int warp = base_node + wi;
    int lane = threadIdx.x & 31;

    float4 a1 = make_float4(0.f, 0.f, 0.f, 0.f);
    float4 a2 = make_float4(0.f, 0.f, 0.f, 0.f);
    __half* ap;
    if (warp < NF) {
        gather_rel(xF, csr_ff, w_ff, row_ff[warp], din_ff[warp], lane, a1);
        gather_rel(xE, csr_ef, w_ef, row_ef[warp], din_ef[warp], lane, a2);
        float s1 = nd_ff[warp], s2 = nd_ef[warp];
        a1.x *= s1; a1.y *= s1; a1.z *= s1; a1.w *= s1;
        a2.x *= s2; a2.y *= s2; a2.z *= s2; a2.w *= s2;
        ap = aggF + (size_t)warp * 256;
    } else {
        int w = warp - NF;
        gather_rel(xF, csr_fE, w_fE, row_fE[w], din_fE[w], lane, a1);
        gather_rel(xE, csr_ee, w_ee, row_ee[w], din_ee[w], lane, a2);
        float s1 = nd_fE[w], s2 = nd_ee[w];
        a1.x *= s1; a1.y *= s1; a1.z *= s1; a1.w *= s1;
        a2.x *= s2; a2.y *= s2; a2.z *= s2; a2.w *= s2;
        ap = aggE + (size_t)w * 256;
    }
    ((uint2*)ap)[lane] = make_uint2(packh2(a1.x, a1.y), packh2(a1.z, a1.w));
    ((uint2*)(ap + 128))[lane] = make_uint2(packh2(a2.x, a2.y), packh2(a2.z, a2.w));
}

// ---------------------------------------------------------------------------
// Dual FP16 mma.sync GEMM (generic): up to two problems; single-problem use
// passes grid.x = nblk1.
// ---------------------------------------------------------------------------
template <int EPI, bool OUTF, bool OUTH, bool AF32>
__global__ void __launch_bounds__(256, 2)
mma_gemm2(const void* __restrict__ A1v, const void* __restrict__ A2v,
          const __half* __restrict__ B1, const __half* __restrict__ B2,
          const float* __restrict__ bias1, const float* __restrict__ bias2,
          const __half* __restrict__ res1, const __half* __restrict__ res2,
          float* __restrict__ Cf1, float* __restrict__ Cf2,
          __half* __restrict__ Ch1, __half* __restrict__ Ch2,
          int M1, int M2, int nblk1, int K, int ldC, float alpha) {
    constexpr int A_BYTES = AF32 ? 128 * 36 * 4 : 128 * 40 * 2;
    constexpr int STAGE = A_BYTES + 128 * 40 * 2;
    extern __shared__ __align__(16) char smem[];
    const uint32_t smbase = smem_u32(smem);

    const bool second = (int)blockIdx.x >= nblk1;
    const int bx = second ? blockIdx.x - nblk1 : blockIdx.x;
    const int M = second ? M2 : M1;
    const void* Av = second ? A2v : A1v;
    const __half* B = second ? B2 : B1;
    const float* bias = second ? bias2 : bias1;
    const __half* resid = second ? res2 : res1;
    float* Cf = second ? Cf2 : Cf1;
    __half* Ch = second ? Ch2 : Ch1;

    const int tid = threadIdx.x;
    const int wid = tid >> 5;
    const int lane = tid & 31;
    const int g = lane >> 2;
    const int tig = lane & 3;
    const int warp_m = (wid & 3) * 32;
    const int warp_n = (wid >> 2) * 64;
    const int row0 = bx * 128;
    const int n0 = blockIdx.y * 128;
    const __half* Bt = B + (size_t)n0 * K;
    const __half* Ah = (const __half*)Av;
    const float* Af = (const float*)Av;

    float c[2][8][4];
#pragma unroll
    for (int mt = 0; mt < 2; mt++)
#pragma unroll
        for (int nt = 0; nt < 8; nt++)
#pragma unroll
            for (int q = 0; q < 4; q++) c[mt][nt][q] = 0.f;

    const int NIT = K >> 5;    // BK = 32

    auto load_stage = [&](int s, int k0) {
        uint32_t sb = smbase + s * STAGE;
        if (AF32) {
#pragma unroll
            for (int i = 0; i < 4; i++) {
                int cid = tid + i * 256;
                int m = cid >> 3, kc = (cid & 7) << 2;
                const float* src = Af + (size_t)(row0 + m) * K + k0 + kc;
                uint32_t dst = sb + (m * 36 + kc) * 4;
                unsigned sz = (row0 + m < M) ? 16u : 0u;
                asm volatile("cp.async.cg.shared.global [%0], [%1], 16, %2;"
                             :: "r"(dst), "l"(src), "r"(sz));
            }
        } else {
#pragma unroll
            for (int i = 0; i < 2; i++) {
                int cid = tid + i * 256;
                int m = cid >> 2, kc = (cid & 3) << 3;
                const __half* src = Ah + (size_t)(row0 + m) * K + k0 + kc;
                uint32_t dst = sb + (m * 40 + kc) * 2;
                unsigned sz = (row0 + m < M) ? 16u : 0u;
                asm volatile("cp.async.cg.shared.global [%0], [%1], 16, %2;"
                             :: "r"(dst), "l"(src), "r"(sz));
            }
        }
#pragma unroll
        for (int i = 0; i < 2; i++) {
            int cid = tid + i * 256;
            int nn = cid >> 2, kc = (cid & 3) << 3;
            const __half* src = Bt + (size_t)nn * K + k0 + kc;
            uint32_t dst = sb + A_BYTES + (nn * 40 + kc) * 2;
            asm volatile("cp.async.cg.shared.global [%0], [%1], 16;"
                         :: "r"(dst), "l"(src));
        }
        asm volatile("cp.async.commit_group;");
    };

    load_stage(0, 0);

    for (int it = 0; it < NIT; it++) {
        int s = it & 1;
        if (it + 1 < NIT) {
            load_stage(s ^ 1, (it + 1) << 5);
            asm volatile("cp.async.wait_group 1;");
        } else {
            asm volatile("cp.async.wait_group 0;");
        }
        __syncthreads();

        char* sbp = smem + s * STAGE;
#pragma unroll
        for (int ks = 0; ks < 2; ks++) {
            const int kb = ks << 4;
            uint32_t a[2][4];
#pragma unroll
            for (int mt = 0; mt < 2; mt++) {
                int mr = warp_m + mt * 16 + g;
                if (AF32) {
                    const float* A32 = (const float*)sbp;
                    float2 f0 = *(const float2*)&A32[mr * 36 + kb + 2 * tig];
                    float2 f1 = *(const float2*)&A32[(mr + 8) * 36 + kb + 2 * tig];
                    float2 f2 = *(const float2*)&A32[mr * 36 + kb + 2 * tig + 8];
                    float2 f3 = *(const float2*)&A32[(mr + 8) * 36 + kb + 2 * tig + 8];
                    a[mt][0] = packh2(f0.x, f0.y);
                    a[mt][1] = packh2(f1.x, f1.y);
                    a[mt][2] = packh2(f2.x, f2.y);
                    a[mt][3] = packh2(f3.x, f3.y);
                } else {
                    const __half* A16 = (const __half*)sbp;
                    a[mt][0] = *(const uint32_t*)&A16[mr * 40 + kb + 2 * tig];
                    a[mt][1] = *(const uint32_t*)&A16[(mr + 8) * 40 + kb + 2 * tig];
                    a[mt][2] = *(const uint32_t*)&A16[mr * 40 + kb + 2 * tig + 8];
                    a[mt][3] = *(const uint32_t*)&A16[(mr + 8) * 40 + kb + 2 * tig + 8];
                }
            }
            const __half* Bs = (const __half*)(sbp + A_BYTES);
            uint32_t b[8][2];
#pragma unroll
            for (int nt = 0; nt < 8; nt++) {
                int nc = warp_n + nt * 8 + g;
                b[nt][0] = *(const uint32_t*)&Bs[nc * 40 + kb + 2 * tig];
                b[nt][1] = *(const uint32_t*)&Bs[nc * 40 + kb + 2 * tig + 8];
            }
#pragma unroll
            for (int mt = 0; mt < 2; mt++)
#pragma unroll
                for (int nt = 0; nt < 8; nt++) {
                    asm volatile(
                        "mma.sync.aligned.m16n8k16.row.col.f32.f16.f16.f32 "
                        "{%0,%1,%2,%3}, {%4,%5,%6,%7}, {%8,%9}, {%0,%1,%2,%3};"
                        : "+f"(c[mt][nt][0]), "+f"(c[mt][nt][1]),
                          "+f"(c[mt][nt][2]), "+f"(c[mt][nt][3])
                        : "r"(a[mt][0]), "r"(a[mt][1]), "r"(a[mt][2]), "r"(a[mt][3]),
                          "r"(b[nt][0]), "r"(b[nt][1]));
                }
        }
        __syncthreads();
    }

    // ---- epilogue ----
#pragma unroll
    for (int nt = 0; nt < 8; nt++) {
        int col = n0 + warp_n + nt * 8 + tig * 2;
        float b0 = bias[col], b1 = bias[col + 1];
#pragma unroll
        for (int mt = 0; mt < 2; mt++) {
#pragma unroll
            for (int h = 0; h < 2; h++) {
                int row = row0 + warp_m + mt * 16 + g + h * 8;
                if (row < M) {
                    float o0 = alpha * c[mt][nt][h * 2 + 0] + b0;
                    float o1 = alpha * c[mt][nt][h * 2 + 1] + b1;
                    if (EPI == 1) { o0 = fmaxf(o0, 0.f); o1 = fmaxf(o1, 0.f); }
                    if (EPI == 2) {
                        __half2 rv = *(const __half2*)(resid + (size_t)row * ldC + col);
                        float2 rf = __half22float2(rv);
                        o0 += rf.x; o1 += rf.y;
                    }
                    if (OUTF)
                        *(float2*)(Cf + (size_t)row * ldC + col) = make_float2(o0, o1);
                    if (OUTH)
                        *(__half2*)(Ch + (size_t)row * ldC + col) =
                            __floats2half2_rn(o0, o1);
                }
            }
        }
    }
}

// ---------------------------------------------------------------------------
// FC GEMM: K=128 resident-A, internal loop over 4 N-tiles (N=512 total).
// ---------------------------------------------------------------------------
#define FC_A_BYTES (4 * 10240)               // 40960
#define FC_SMEM    (FC_A_BYTES + 2 * 10240)  // 61440

__global__ void __launch_bounds__(256, 2)
mma_fc2(const __half* __restrict__ A1, const __half* __restrict__ A2,
        const __half* __restrict__ B1, const __half* __restrict__ B2,
        const float* __restrict__ bias1, const float* __restrict__ bias2,
        float* __restrict__ Cf1, float* __restrict__ Cf2,
        int M1, int M2, int nblk1) {
    extern __shared__ __align__(16) char smem[];
    const uint32_t smbase = smem_u32(smem);

    const bool second = (int)blockIdx.x >= nblk1;
    const int bx = second ? blockIdx.x - nblk1 : blockIdx.x;
    const int M = second ? M2 : M1;
    const __half* A = second ? A2 : A1;
    const __half* B = second ? B2 : B1;
    const float* bias = second ? bias2 : bias1;
    float* Cf = second ? Cf2 : Cf1;

    const int tid = threadIdx.x;
    const int wid = tid >> 5;
    const int lane = tid & 31;
    const int g = lane >> 2;
    const int tig = lane & 3;
    const int warp_m = (wid & 3) * 32;
    const int warp_n = (wid >> 2) * 64;
    const int row0 = bx * 128;

#pragma unroll
    for (int chunk = 0; chunk < 4; chunk++) {
#pragma unroll
        for (int i = 0; i < 2; i++) {
            int cid = tid + i * 256;
            int m = cid >> 2, kc = (cid & 3) << 3;
            const __half* src = A + (size_t)(row0 + m) * HID + chunk * 32 + kc;
            uint32_t dst = smbase + chunk * 10240 + (m * 40 + kc) * 2;
            unsigned sz = (row0 + m < M) ? 16u : 0u;
            asm volatile("cp.async.cg.shared.global [%0], [%1], 16, %2;"
                         :: "r"(dst), "l"(src), "r"(sz));
        }
    }
    auto load_b = [&](int gi) {
        int y = gi >> 2, it = gi & 3;
        uint32_t sb = smbase + FC_A_BYTES + (gi & 1) * 10240;
        const __half* Bt = B + (size_t)(y * 128) * HID + it * 32;
#pragma unroll
        for (int i = 0; i < 2; i++) {
            int cid = tid + i * 256;
            int nn = cid >> 2, kc = (cid & 3) << 3;
            const __half* src = Bt + (size_t)nn * HID + kc;
            uint32_t dst = sb + (nn * 40 + kc) * 2;
            asm volatile("cp.async.cg.shared.global [%0], [%1], 16;"
                         :: "r"(dst), "l"(src));
        }
        asm volatile("cp.async.commit_group;");
    };

    load_b(0);

    float c[2][8][4];
#pragma unroll
    for (int mt = 0; mt < 2; mt++)
#pragma unroll
        for (int nt = 0; nt < 8; nt++)
#pragma unroll
            for (int q = 0; q < 4; q++) c[mt][nt][q] = 0.f;

    for (int gi = 0; gi < 16; gi++) {
        if (gi + 1 < 16) {
            load_b(gi + 1);
            asm volatile("cp.async.wait_group 1;");
        } else {
            asm volatile("cp.async.wait_group 0;");
        }
        __syncthreads();

        const __half* As = (const __half*)(smem + (gi & 3) * 10240);
        const __half* Bs = (const __half*)(smem + FC_A_BYTES + (gi & 1) * 10240);
#pragma unroll
        for (int ks = 0; ks < 2; ks++) {
            const int kb = ks << 4;
            uint32_t a[2][4];
#pragma unroll
            for (int mt = 0; mt < 2; mt++) {
                int mr = warp_m + mt * 16 + g;
                a[mt][0] = *(const uint32_t*)&As[mr * 40 + kb + 2 * tig];
                a[mt][1] = *(const uint32_t*)&As[(mr + 8) * 40 + kb + 2 * tig];
                a[mt][2] = *(const uint32_t*)&As[mr * 40 + kb + 2 * tig + 8];
                a[mt][3] = *(const uint32_t*)&As[(mr + 8) * 40 + kb + 2 * tig + 8];
            }
            uint32_t b[8][2];
#pragma unroll
            for (int nt = 0; nt < 8; nt++) {
                int nc = warp_n + nt * 8 + g;
                b[nt][0] = *(const uint32_t*)&Bs[nc * 40 + kb + 2 * tig];
                b[nt][1] = *(const uint32_t*)&Bs[nc * 40 + kb + 2 * tig + 8];
            }
#pragma unroll
            for (int mt = 0; mt < 2; mt++)
#pragma unroll
                for (int nt = 0; nt < 8; nt++) {
                    asm volatile(
                        "mma.sync.aligned.m16n8k16.row.col.f32.f16.f16.f32 "
                        "{%0,%1,%2,%3}, {%4,%5,%6,%7}, {%8,%9}, {%0,%1,%2,%3};"
                        : "+f"(c[mt][nt][0]), "+f"(c[mt][nt][1]),
                          "+f"(c[mt][nt][2]), "+f"(c[mt][nt][3])
                        : "r"(a[mt][0]), "r"(a[mt][1]), "r"(a[mt][2]), "r"(a[mt][3]),
                          "r"(b[nt][0]), "r"(b[nt][1]));
                }
        }
        __syncthreads();

        if ((gi & 3) == 3) {
            int y = gi >> 2;
#pragma unroll
            for (int nt = 0; nt < 8; nt++) {
                int col = y * 128 + warp_n + nt * 8 + tig * 2;
                float b0 = bias[col], b1 = bias[col + 1];
#pragma unroll
                for (int mt = 0; mt < 2; mt++) {
#pragma unroll
                    for (int h = 0; h < 2; h++) {
                        int row = row0 + warp_m + mt * 16 + g + h * 8;
                        if (row < M) {
                            float o0 = c[mt][nt][h * 2 + 0] + b0;
                            float o1 = c[mt][nt][h * 2 + 1] + b1;
                            *(float2*)(Cf + (size_t)row * RAW + col) =
                                make_float2(o0, o1);
                        }
                    }
                }
            }
#pragma unroll
            for (int mt = 0; mt < 2; mt++)
#pragma unroll
                for (int nt = 0; nt < 8; nt++)
#pragma unroll
                    for (int q = 0; q < 4; q++) c[mt][nt][q] = 0.f;
        }
    }
}

#define SMEM_H  (2 * (128 * 40 * 2 + 128 * 40 * 2))           // 40960
#define SMEM_F  (2 * (128 * 36 * 4 + 128 * 40 * 2))           // 57344

// ---------------------------------------------------------------------------
// Host launch
// ---------------------------------------------------------------------------
extern "C" void kernel_launch(void* const* d_in, const int* in_sizes, int n_in,
                              void* d_out, int out_size) {
    const float* frame = (const float*)d_in[0];
    const float* fe    = (const float*)d_in[1];
    const int* s_ff = (const int*)d_in[2];  const int* d_ff = (const int*)d_in[3];
    const int* s_fE = (const int*)d_in[4];  const int* d_fE = (const int*)d_in[5];  // frfe
    const int* s_ef = (const int*)d_in[6];  const int* d_ef = (const int*)d_in[7];  // fefr
    const int* s_ee = (const int*)d_in[8];  const int* d_ee = (const int*)d_in[9];
    const float* W_fr_lin = (const float*)d_in[10]; const float* b_fr_lin = (const float*)d_in[11];
    const float* W_fe_lin = (const float*)d_in[12]; const float* b_fe_lin = (const float*)d_in[13];
    const float* W_frfr = (const float*)d_in[14];   const float* b_frfr = (const float*)d_in[15];
    const float* W_frfe = (const float*)d_in[16];   const float* b_frfe = (const float*)d_in[17];
    const float* W_fefr = (const float*)d_in[18];   const float* b_fefr = (const float*)d_in[19];
    const float* W_fefe = (const float*)d_in[20];   const float* b_fefe = (const float*)d_in[21];
    const float* W_fr_fc = (const float*)d_in[22];  const float* b_fr_fc = (const float*)d_in[23];
    const float* W_fe_fc = (const float*)d_in[24];  const float* b_fe_fc = (const float*)d_in[25];

    __half *x_fr16, *x_fe16, *h_fr16, *h_fe16, *h2_fr16, *h2_fe16, *aggF, *aggE;
    __half *WlinF_t, *WlinE_t, *WcatF_t, *WcatE_t, *WfcF_t, *WfcE_t;
    float *deg, *bias_gF, *bias_gE;
    int *ideg, *csr_ff, *csr_ef, *csr_fE, *csr_ee;
    float *w_ff, *w_ef, *w_fE, *w_ee;
    int *row_ff, *cur_ff, *row_ef, *cur_ef, *row_fE, *cur_fE, *row_ee, *cur_ee;
    int *part, *bsum;
    cudaGetSymbolAddress((void**)&x_fr16, g_x_fr16);
    cudaGetSymbolAddress((void**)&x_fe16, g_x_fe16);
    cudaGetSymbolAddress((void**)&h_fr16, g_h_fr16);
    cudaGetSymbolAddress((void**)&h_fe16, g_h_fe16);
    cudaGetSymbolAddress((void**)&h2_fr16, g_h2_fr16);
    cudaGetSymbolAddress((void**)&h2_fe16, g_h2_fe16);
    cudaGetSymbolAddress((void**)&aggF, g_aggF);
    cudaGetSymbolAddress((void**)&aggE, g_aggE);
    cudaGetSymbolAddress((void**)&ideg, g_ideg);
    cudaGetSymbolAddress((void**)&deg, g_deg);
    cudaGetSymbolAddress((void**)&WlinF_t, g_WlinF_t);
    cudaGetSymbolAddress((void**)&WlinE_t, g_WlinE_t);
    cudaGetSymbolAddress((void**)&WcatF_t, g_WcatF_t);
    cudaGetSymbolAddress((void**)&WcatE_t, g_WcatE_t);
    cudaGetSymbolAddress((void**)&WfcF_t, g_WfcF_t);
    cudaGetSymbolAddress((void**)&WfcE_t, g_WfcE_t);
    cudaGetSymbolAddress((void**)&bias_gF, g_bias_gF);
    cudaGetSymbolAddress((void**)&bias_gE, g_bias_gE);
    cudaGetSymbolAddress((void**)&csr_ff, g_csr_ff);
    cudaGetSymbolAddress((void**)&csr_ef, g_csr_ef);
    cudaGetSymbolAddress((void**)&csr_fE, g_csr_fE);
    cudaGetSymbolAddress((void**)&csr_ee, g_csr_ee);
    cudaGetSymbolAddress((void**)&w_ff, g_wcsr_ff);
    cudaGetSymbolAddress((void**)&w_ef, g_wcsr_ef);
    cudaGetSymbolAddress((void**)&w_fE, g_wcsr_fE);
    cudaGetSymbolAddress((void**)&w_ee, g_wcsr_ee);
    cudaGetSymbolAddress((void**)&row_ff, g_row_ff);
    cudaGetSymbolAddress((void**)&cur_ff, g_cur_ff);
    cudaGetSymbolAddress((void**)&row_ef, g_row_ef);
    cudaGetSymbolAddress((void**)&cur_ef, g_cur_ef);
    cudaGetSymbolAddress((void**)&row_fE, g_row_fE);
    cudaGetSymbolAddress((void**)&cur_fE, g_cur_fE);
    cudaGetSymbolAddress((void**)&row_ee, g_row_ee);
    cudaGetSymbolAddress((void**)&cur_ee, g_cur_ee);
    cudaGetSymbolAddress((void**)&part, g_part);
    cudaGetSymbolAddress((void**)&bsum, g_bsum);

    cudaFuncSetAttribute(mma_gemm2<0, false, true, true>,
                         cudaFuncAttributeMaxDynamicSharedMemorySize, SMEM_F);
    cudaFuncSetAttribute(mma_gemm2<1, false, true, false>,
                         cudaFuncAttributeMaxDynamicSharedMemorySize, SMEM_H);
    cudaFuncSetAttribute(mma_gemm2<2, true, true, false>,
                         cudaFuncAttributeMaxDynamicSharedMemorySize, SMEM_H);
    cudaFuncSetAttribute(mma_fc2,
                         cudaFuncAttributeMaxDynamicSharedMemorySize, FC_SMEM);

    // degree layout
    int* id_out_ff = ideg;
    int* id_in_ff  = ideg + NF;
    int* id_out_fE = ideg + 2 * (size_t)NF;
    int* id_in_ef  = ideg + 3 * (size_t)NF;
    int* id_in_fE  = ideg + 4 * (size_t)NF;
    int* id_out_ef = ideg + 4 * (size_t)NF + NE;
    int* id_out_ee = ideg + 4 * (size_t)NF + 2 * (size_t)NE;
    int* id_in_ee  = ideg + 4 * (size_t)NF + 3 * (size_t)NE;

    float* ns_ff = deg;
    float* nd_ff = deg + NF;
    float* ns_fE = deg + 2 * (size_t)NF;
    float* nd_ef = deg + 3 * (size_t)NF;
    float* nd_fE = deg + 4 * (size_t)NF;
    float* ns_ef = deg + 4 * (size_t)NF + NE;
    float* ns_ee = deg + 4 * (size_t)NF + 2 * (size_t)NE;
    float* nd_ee = deg + 4 * (size_t)NF + 3 * (size_t)NE;

    float* out = (float*)d_out;
    float* o_frh = out;
    float* o_feh = out + (size_t)NF * RAW;
    float* o_hfr = o_feh + (size_t)NE * RAW;
    float* o_hfe = o_hfr + (size_t)NF * HID;

    const int T = 256;
    const size_t degN = (size_t)4 * NF + (size_t)4 * NE;
    const int eb = (NEDGE + T - 1) / T;
    const int nbF = (NF + 255) / 256;   // 391
    const int nbE = (NE + 255) / 256;   // 782

    cudaStream_t s2;
    cudaStreamCreateWithFlags(&s2, cudaStreamNonBlocking);
    cudaEvent_t evFork, evJoin, evX, e1F, e1E, evEnd;
    cudaEventCreateWithFlags(&evFork, cudaEventDisableTiming);
    cudaEventCreateWithFlags(&evJoin, cudaEventDisableTiming);
    cudaEventCreateWithFlags(&evX, cudaEventDisableTiming);
    cudaEventCreateWithFlags(&e1F, cudaEventDisableTiming);
    cudaEventCreateWithFlags(&e1E, cudaEventDisableTiming);
    cudaEventCreateWithFlags(&evEnd, cudaEventDisableTiming);

    // ---- fork ----
    cudaEventRecord(evFork, 0);
    cudaStreamWaitEvent(s2, evFork, 0);

    // side stream: degrees, norms, CSR build
    zero_kernel<<<(unsigned)((degN / 4 + T - 1) / T), T, 0, s2>>>(
        (float*)ideg, degN / 4);
    deg_all_kernel<<<dim3(eb, 4), T, 0, s2>>>(
        s_ff, d_ff, s_ef, d_ef, s_fE, d_fE, s_ee, d_ee,
        id_out_ff, id_in_ff, id_out_ef, id_in_ef,
        id_out_fE, id_in_fE, id_out_ee, id_in_ee, NEDGE);
    norm_kernel<<<(unsigned)((degN + T - 1) / T), T, 0, s2>>>(ideg, deg, (int)degN);
    scan_partial4<<<dim3(nbE, 4), 256, 0, s2>>>(
        id_in_ff, id_in_ef, id_in_fE, id_in_ee, part, bsum, NF, NF, NE, NE);
    scan_bsum4<<<4, 1024, 0, s2>>>(bsum, nbF, nbF, nbE, nbE);
    scan_add4<<<dim3(nbE, 4), 256, 0, s2>>>(part, bsum,
                                            row_ff, cur_ff, row_ef, cur_ef,
                                            row_fE, cur_fE, row_ee, cur_ee,
                                            NF, NF, NE, NE);
    fill4<<<dim3(eb, 4), T, 0, s2>>>(s_ff, d_ff, s_ef, d_ef, s_fE, d_fE, s_ee, d_ee,
                                     ns_ff, ns_ef, ns_fE, ns_ee,
                                     cur_ff, csr_ff, w_ff, cur_ef, csr_ef, w_ef,
                                     cur_fE, csr_fE, w_fE, cur_ee, csr_ee, w_ee,
                                     NEDGE);
    cudaEventRecord(evJoin, s2);

    // main stream: weight prep + input linears
    wprep_kernel<<<(295168 + T - 1) / T, T>>>(
        W_fr_lin, W_fe_lin, W_frfr, W_fefr, W_frfe, W_fefe, W_fr_fc, W_fe_fc,
        b_frfr, b_fefr, b_frfe, b_fefe,
        WlinF_t, WlinE_t, WcatF_t, WcatE_t, WfcF_t, WfcE_t, bias_gF, bias_gE);

    const int gFx = (NF + 127) / 128;   // 782
    const int gEx = (NE + 127) / 128;   // 1563
    const int gAll = gFx + gEx;         // 2345
    const unsigned gwF = ((unsigned)NF * 32 + T - 1) / T;
    const unsigned gwE = ((unsigned)NE * 32 + T - 1) / T;

    mma_gemm2<0, false, true, true><<<dim3(gAll, 1), 256, SMEM_F>>>(
        frame, fe, WlinF_t, WlinE_t, b_fr_lin, b_fe_lin, nullptr, nullptr,
        nullptr, nullptr, x_fr16, x_fe16, NF, NE, gFx, RAW, HID, 1.f);
    cudaStreamWaitEvent(0, evJoin, 0);       // CSR ready
    cudaEventRecord(evX, 0);                 // x + CSR ready
    cudaStreamWaitEvent(s2, evX, 0);

    // ==== layer 1: F-chain on main, E-chain on s2 ====
    gather_all<<<gwF, T>>>(x_fr16, x_fe16,
                           csr_ff, w_ff, row_ff, id_in_ff, nd_ff,
                           csr_ef, w_ef, row_ef, id_in_ef, nd_ef,
                           csr_fE, w_fE, row_fE, id_in_fE, nd_fE,
                           csr_ee, w_ee, row_ee, id_in_ee, nd_ee,
                           aggF, aggE, 0, NF);
    mma_gemm2<1, false, true, false><<<dim3(gFx, 1), 256, SMEM_H>>>(
        aggF, nullptr, WcatF_t, nullptr, bias_gF, nullptr, nullptr, nullptr,
        nullptr, nullptr, h_fr16, nullptr, NF, 0, gFx, 256, HID, 0.5f);
    cudaEventRecord(e1F, 0);

    gather_all<<<gwE, T, 0, s2>>>(x_fr16, x_fe16,
                                  csr_ff, w_ff, row_ff, id_in_ff, nd_ff,
                                  csr_ef, w_ef, row_ef, id_in_ef, nd_ef,
                                  csr_fE, w_fE, row_fE, id_in_fE, nd_fE,
                                  csr_ee, w_ee, row_ee, id_in_ee, nd_ee,
                                  aggF, aggE, NF, NE);
    mma_gemm2<1, false, true, false><<<dim3(gEx, 1), 256, SMEM_H, s2>>>(
        aggE, nullptr, WcatE_t, nullptr, bias_gE, nullptr, nullptr, nullptr,
        nullptr, nullptr, h_fe16, nullptr, NE, 0, gEx, 256, HID, 0.5f);
    cudaEventRecord(e1E, s2);

    // ==== layer 2 ====
    cudaStreamWaitEvent(0, e1E, 0);          // F gather needs h_fe too
    gather_all<<<gwF, T>>>(h_fr16, h_fe16,
                           csr_ff, w_ff, row_ff, id_in_ff, nd_ff,
                           csr_ef, w_ef, row_ef, id_in_ef, nd_ef,
                           csr_fE, w_fE, row_fE, id_in_fE, nd_fE,
                           csr_ee, w_ee, row_ee, id_in_ee, nd_ee,
                           aggF, aggE, 0, NF);
    mma_gemm2<2, true, true, false><<<dim3(gFx, 1), 256, SMEM_H>>>(
        aggF, nullptr, WcatF_t, nullptr, bias_gF, nullptr, x_fr16, nullptr,
        o_hfr, nullptr, h2_fr16, nullptr, NF, 0, gFx, 256, HID, 0.5f);
    // FC for F right away on main (needs only h2_fr)
    mma_fc2<<<dim3(gFx, 1), 256, FC_SMEM>>>(
        h2_fr16, nullptr, WfcF_t, nullptr, b_fr_fc, nullptr,
        o_frh, nullptr, NF, 0, gFx);

    cudaStreamWaitEvent(s2, e1F, 0);         // E gather needs h_fr too
    gather_all<<<gwE, T, 0, s2>>>(h_fr16, h_fe16,
                                  csr_ff, w_ff, row_ff, id_in_ff, nd_ff,
                                  csr_ef, w_ef, row_ef, id_in_ef, nd_ef,
                                  csr_fE, w_fE, row_fE, id_in_fE, nd_fE,
                                  csr_ee, w_ee, row_ee, id_in_ee, nd_ee,
                                  aggF, aggE, NF, NE);
    mma_gemm2<2, true, true, false><<<dim3(gEx, 1), 256, SMEM_H, s2>>>(
        aggE, nullptr, WcatE_t, nullptr, bias_gE, nullptr, x_fe16, nullptr,
        o_hfe, nullptr, h2_fe16, nullptr, NE, 0, gEx, 256, HID, 0.5f);
    mma_fc2<<<dim3(gEx, 1), 256, FC_SMEM, s2>>>(
        h2_fe16, nullptr, WfcE_t, nullptr, b_fe_fc, nullptr,
        o_feh, nullptr, NE, 0, gEx);
    cudaEventRecord(evEnd, s2);
    cudaStreamWaitEvent(0, evEnd, 0);        // join everything back
}

// round 16
// speedup vs baseline: 1.0217x; 1.0217x over previous
#include <cuda_runtime.h>
#include <cuda_fp16.h>
#include <cstdint>
#include <cstddef>

// ---------------------------------------------------------------------------
// Problem constants
// ---------------------------------------------------------------------------
#define NF 100000
#define NE 200000
#define HID 128
#define RAW 512
#define NEDGE 1000000

// ---------------------------------------------------------------------------
// Scratch (device globals -- no allocation allowed)
// ---------------------------------------------------------------------------
__device__ __half g_x_fr16[(size_t)NF * HID];
__device__ __half g_x_fe16[(size_t)NE * HID];
__device__ __half g_h_fr16[(size_t)NF * HID];
__device__ __half g_h_fe16[(size_t)NE * HID];
__device__ __half g_h2_fr16[(size_t)NF * HID];
__device__ __half g_h2_fe16[(size_t)NE * HID];
__device__ __half g_aggF[(size_t)NF * 256];
__device__ __half g_aggE[(size_t)NE * 256];
__device__ int    g_ideg[(size_t)4 * NF + (size_t)4 * NE];
__device__ float  g_deg[(size_t)4 * NF + (size_t)4 * NE];
__device__ __half g_WlinF_t[(size_t)HID * RAW];
__device__ __half g_WlinE_t[(size_t)HID * RAW];
__device__ __half g_WcatF_t[(size_t)HID * 256];
__device__ __half g_WcatE_t[(size_t)HID * 256];
__device__ __half g_WfcF_t[(size_t)RAW * HID];
__device__ __half g_WfcE_t[(size_t)RAW * HID];
__device__ float  g_bias_gF[HID];
__device__ float  g_bias_gE[HID];
__device__ int g_csr_ff[NEDGE];
__device__ int g_csr_ef[NEDGE];
__device__ int g_csr_fE[NEDGE];
__device__ int g_csr_ee[NEDGE];
__device__ int g_row_ff[NF];  __device__ int g_cur_ff[NF];
__device__ int g_row_ef[NF];  __device__ int g_cur_ef[NF];
__device__ int g_row_fE[NE];  __device__ int g_cur_fE[NE];
__device__ int g_row_ee[NE];  __device__ int g_cur_ee[NE];
__device__ int g_part[(size_t)4 * NE];
__device__ int g_bsum[4 * 1024];

// ---------------------------------------------------------------------------
// Helpers
// ---------------------------------------------------------------------------
__device__ __forceinline__ uint32_t smem_u32(const void* p) {
    uint32_t r;
    asm("{ .reg .u64 t; cvta.to.shared.u64 t, %1; cvt.u32.u64 %0, t; }"
        : "=r"(r) : "l"(p));
    return r;
}

__device__ __forceinline__ uint32_t packh2(float x, float y) {
    __half2 h = __floats2half2_rn(x, y);
    return *(uint32_t*)&h;
}

// ---------------------------------------------------------------------------
// Consolidated prep kernels
// ---------------------------------------------------------------------------
__global__ void zero_kernel(float* __restrict__ p, size_t n4) {
    size_t i = (size_t)blockIdx.x * blockDim.x + threadIdx.x;
    if (i < n4) ((float4*)p)[i] = make_float4(0.f, 0.f, 0.f, 0.f);
}

__global__ void wprep_kernel(
    const float* __restrict__ WlinF, const float* __restrict__ WlinE,
    const float* __restrict__ W_frfr, const float* __restrict__ W_fefr,
    const float* __restrict__ W_frfe, const float* __restrict__ W_fefe,
    const float* __restrict__ WfcF, const float* __restrict__ WfcE,
    const float* __restrict__ b_frfr, const float* __restrict__ b_fefr,
    const float* __restrict__ b_frfe, const float* __restrict__ b_fefe,
    __half* __restrict__ oLinF, __half* __restrict__ oLinE,
    __half* __restrict__ oCatF, __half* __restrict__ oCatE,
    __half* __restrict__ oFcF, __half* __restrict__ oFcE,
    float* __restrict__ obF, float* __restrict__ obE) {
    int idx = blockIdx.x * blockDim.x + threadIdx.x;
    if (idx < 65536) {                                    // WlinX_t [128][512]
        int n = idx >> 9, k = idx & 511;
        oLinF[idx] = __float2half(WlinF[(size_t)k * HID + n]);
        oLinE[idx] = __float2half(WlinE[(size_t)k * HID + n]);
        return;
    }
    idx -= 65536;
    if (idx < 32768) {                                    // Wcat [128][256]
        int n = idx >> 8, k = idx & 255;
        float vF = (k < 128) ? W_frfr[(size_t)k * 128 + n]
                             : W_fefr[(size_t)(k - 128) * 128 + n];
        float vE = (k < 128) ? W_frfe[(size_t)k * 128 + n]
                             : W_fefe[(size_t)(k - 128) * 128 + n];
        oCatF[idx] = __float2half(vF);
        oCatE[idx] = __float2half(vE);
        return;
    }
    idx -= 32768;
    if (idx < 65536) {                                    // Wfc_t [512][128]
        int n = idx >> 7, k = idx & 127;
        oFcF[idx] = __float2half(WfcF[(size_t)k * RAW + n]);
        oFcE[idx] = __float2half(WfcE[(size_t)k * RAW + n]);
        return;
    }
    idx -= 65536;
    if (idx < 128) {
        obF[idx] = 0.5f * (b_frfr[idx] + b_fefr[idx]);
        obE[idx] = 0.5f * (b_frfe[idx] + b_fefe[idx]);
    }
}

__global__ void deg_all_kernel(
    const int* __restrict__ s0, const int* __restrict__ d0,
    const int* __restrict__ s1, const int* __restrict__ d1,
    const int* __restrict__ s2, const int* __restrict__ d2,
    const int* __restrict__ s3, const int* __restrict__ d3,
    int* __restrict__ o0, int* __restrict__ i0,
    int* __restrict__ o1, int* __restrict__ i1,
    int* __restrict__ o2, int* __restrict__ i2,
    int* __restrict__ o3, int* __restrict__ i3, int n) {
    int i = blockIdx.x * blockDim.x + threadIdx.x;
    if (i >= n) return;
    switch (blockIdx.y) {
        case 0: atomicAdd(&o0[s0[i]], 1); atomicAdd(&i0[d0[i]], 1); break;
        case 1: atomicAdd(&o1[s1[i]], 1); atomicAdd(&i1[d1[i]], 1); break;
        case 2: atomicAdd(&o2[s2[i]], 1); atomicAdd(&i2[d2[i]], 1); break;
        default: atomicAdd(&o3[s3[i]], 1); atomicAdd(&i3[d3[i]], 1); break;
    }
}

__global__ void norm_kernel(const int* __restrict__ d, float* __restrict__ p, int n) {
    int i = blockIdx.x * blockDim.x + threadIdx.x;
    if (i < n) {
        int v = d[i];
        p[i] = (v > 0) ? rsqrtf((float)v) : 0.f;
    }
}

// ---------------------------------------------------------------------------
// Batched CSR build: 4 relations per launch (grid.y = relation)
// ---------------------------------------------------------------------------
__global__ void scan_partial4(
    const int* __restrict__ in0, const int* __restrict__ in1,
    const int* __restrict__ in2, const int* __restrict__ in3,
    int* __restrict__ part, int* __restrict__ bsum,
    int n0, int n1, int n2, int n3) {
    int rel = blockIdx.y;
    const int* in = rel == 0 ? in0 : rel == 1 ? in1 : rel == 2 ? in2 : in3;
    int n = rel == 0 ? n0 : rel == 1 ? n1 : rel == 2 ? n2 : n3;
    if (blockIdx.x * 256 >= n) return;
    __shared__ int sh[256];
    int t = threadIdx.x;
    int i = blockIdx.x * 256 + t;
    int v = (i < n) ? in[i] : 0;
    sh[t] = v;
    __syncthreads();
#pragma unroll
    for (int off = 1; off < 256; off <<= 1) {
        int u = (t >= off) ? sh[t - off] : 0;
        __syncthreads();
        sh[t] += u;
        __syncthreads();
    }
    if (i < n) part[(size_t)rel * NE + i] = sh[t] - v;
    if (t == 255) bsum[rel * 1024 + blockIdx.x] = sh[255];
}

__global__ void scan_bsum4(int* __restrict__ bsum, int nb0, int nb1, int nb2, int nb3) {
    int rel = blockIdx.x;
    int nb = rel == 0 ? nb0 : rel == 1 ? nb1 : rel == 2 ? nb2 : nb3;
    int* bs = bsum + rel * 1024;
    __shared__ int sh[1024];
    int t = threadIdx.x;
    int v = (t < nb) ? bs[t] : 0;
    sh[t] = v;
    __syncthreads();
#pragma unroll
    for (int off = 1; off < 1024; off <<= 1) {
        int u = (t >= off) ? sh[t - off] : 0;
        __syncthreads();
        sh[t] += u;
        __syncthreads();
    }
    if (t < nb) bs[t] = sh[t] - v;
}

__global__ void scan_add4(
    const int* __restrict__ part, const int* __restrict__ bsum,
    int* __restrict__ row0, int* __restrict__ cur0,
    int* __restrict__ row1, int* __restrict__ cur1,
    int* __restrict__ row2, int* __restrict__ cur2,
    int* __restrict__ row3, int* __restrict__ cur3,
    int n0, int n1, int n2, int n3) {
    int rel = blockIdx.y;
    int n = rel == 0 ? n0 : rel == 1 ? n1 : rel == 2 ? n2 : n3;
    int i = blockIdx.x * 256 + threadIdx.x;
    if (i >= n) return;
    int v = part[(size_t)rel * NE + i] + bsum[rel * 1024 + blockIdx.x];
    switch (rel) {
        case 0: row0[i] = v; cur0[i] = v; break;
        case 1: row1[i] = v; cur1[i] = v; break;
        case 2: row2[i] = v; cur2[i] = v; break;
        default: row3[i] = v; cur3[i] = v; break;
    }
}

__global__ void fill4(
    const int* __restrict__ s0, const int* __restrict__ d0,
    const int* __restrict__ s1, const int* __restrict__ d1,
    const int* __restrict__ s2, const int* __restrict__ d2,
    const int* __restrict__ s3, const int* __restrict__ d3,
    int* __restrict__ c0, int* __restrict__ r0,
    int* __restrict__ c1, int* __restrict__ r1,
    int* __restrict__ c2, int* __restrict__ r2,
    int* __restrict__ c3, int* __restrict__ r3, int n) {
    int i = blockIdx.x * blockDim.x + threadIdx.x;
    if (i >= n) return;
    switch (blockIdx.y) {
        case 0: r0[atomicAdd(&c0[d0[i]], 1)] = s0[i]; break;
        case 1: r1[atomicAdd(&c1[d1[i]], 1)] = s1[i]; break;
        case 2: r2[atomicAdd(&c2[d2[i]], 1)] = s2[i]; break;
        default: r3[atomicAdd(&c3[d3[i]], 1)] = s3[i]; break;
    }
}

// ---------------------------------------------------------------------------
// Gather aggregation over a node range [base, base+count):
// node id < NF -> F-dst (rels ff, ef) -> aggF.  else -> E-dst -> aggE.
// ---------------------------------------------------------------------------
__device__ __forceinline__ void gather_rel(const __half* __restrict__ x,
                                           const int* __restrict__ csr,
                                           int start, int dc,
                                           const float* __restrict__ ns,
                                           int lane, float4& a) {
    for (int base = 0; base < dc; base += 32) {
        int e = base + lane;
        int sidx = 0; float wv = 0.f;
        if (e < dc) { sidx = csr[start + e]; wv = __ldg(&ns[sidx]); }
        int m = min(32, dc - base);
        for (int j = 0; j < m; j++) {
            int s = __shfl_sync(0xffffffffu, sidx, j);
            float w = __shfl_sync(0xffffffffu, wv, j);
            uint2 raw = __ldg(&((const uint2*)(x + (size_t)s * HID))[lane]);
            float2 f0 = __half22float2(*(__half2*)&raw.x);
            float2 f1 = __half22float2(*(__half2*)&raw.y);
            a.x += f0.x * w; a.y += f0.y * w;
            a.z += f1.x * w; a.w += f1.y * w;
        }
    }
}

__global__ void __launch_bounds__(256)
gather_all(const __half* __restrict__ xF, const __half* __restrict__ xE,
           const int* __restrict__ csr_ff, const int* __restrict__ row_ff,
           const int* __restrict__ din_ff, const float* __restrict__ ns_ff,
           const float* __restrict__ nd_ff,
           const int* __restrict__ csr_ef, const int* __restrict__ row_ef,
           const int* __restrict__ din_ef, const float* __restrict__ ns_ef,
           const float* __restrict__ nd_ef,
           const int* __restrict__ csr_fE, const int* __restrict__ row_fE,
           const int* __restrict__ din_fE, const float* __restrict__ ns_fE,
           const float* __restrict__ nd_fE,
           const int* __restrict__ csr_ee, const int* __restrict__ row_ee,
           const int* __restrict__ din_ee, const float* __restrict__ ns_ee,
           const float* __restrict__ nd_ee,
           __half* __restrict__ aggF, __half* __restrict__ aggE,
           int base_node, int count) {
    int wi = (blockIdx.x * blockDim.x + threadIdx.x) >> 5;
    if (wi >= count) return;
    int warp = base_node + wi;
    int lane = threadIdx.x & 31;

    float4 a1 = make_float4(0.f, 0.f, 0.f, 0.f);
    float4 a2 = make_float4(0.f, 0.f, 0.f, 0.f);
    __half* ap;
    if (warp < NF) {
        gather_rel(xF, csr_ff, row_ff[warp], din_ff[warp], ns_ff, lane, a1);
        gather_rel(xE, csr_ef, row_ef[warp], din_ef[warp], ns_ef, lane, a2);
        float s1 = nd_ff[warp], s2 = nd_ef[warp];
        a1.x *= s1; a1.y *= s1; a1.z *= s1; a1.w *= s1;
        a2.x *= s2; a2.y *= s2; a2.z *= s2; a2.w *= s2;
        ap = aggF + (size_t)warp * 256;
    } else {
        int w = warp - NF;
        gather_rel(xF, csr_fE, row_fE[w], din_fE[w], ns_fE, lane, a1);
        gather_rel(xE, csr_ee, row_ee[w], din_ee[w], ns_ee, lane, a2);
        float s1 = nd_fE[w], s2 = nd_ee[w];
        a1.x *= s1; a1.y *= s1; a1.z *= s1; a1.w *= s1;
        a2.x *= s2; a2.y *= s2; a2.z *= s2; a2.w *= s2;
        ap = aggE + (size_t)w * 256;
    }
    ((uint2*)ap)[lane] = make_uint2(packh2(a1.x, a1.y), packh2(a1.z, a1.w));
    ((uint2*)(ap + 128))[lane] = make_uint2(packh2(a2.x, a2.y), packh2(a2.z, a2.w));
}

// ---------------------------------------------------------------------------
// Dual FP16 mma.sync GEMM (generic): up to two problems; single-problem use
// passes grid.x = nblk1.
// ---------------------------------------------------------------------------
template <int EPI, bool OUTF, bool OUTH, bool AF32>
__global__ void __launch_bounds__(256, 2)
mma_gemm2(const void* __restrict__ A1v, const void* __restrict__ A2v,
          const __half* __restrict__ B1, const __half* __restrict__ B2,
          const float* __restrict__ bias1, const float* __restrict__ bias2,
          const __half* __restrict__ res1, const __half* __restrict__ res2,
          float* __restrict__ Cf1, float* __restrict__ Cf2,
          __half* __restrict__ Ch1, __half* __restrict__ Ch2,
          int M1, int M2, int nblk1, int K, int ldC, float alpha) {
    constexpr int A_BYTES = AF32 ? 128 * 36 * 4 : 128 * 40 * 2;
    constexpr int STAGE = A_BYTES + 128 * 40 * 2;
    extern __shared__ __align__(16) char smem[];
    const uint32_t smbase = smem_u32(smem);

    const bool second = (int)blockIdx.x >= nblk1;
    const int bx = second ? blockIdx.x - nblk1 : blockIdx.x;
    const int M = second ? M2 : M1;
    const void* Av = second ? A2v : A1v;
    const __half* B = second ? B2 : B1;
    const float* bias = second ? bias2 : bias1;
    const __half* resid = second ? res2 : res1;
    float* Cf = second ? Cf2 : Cf1;
    __half* Ch = second ? Ch2 : Ch1;

    const int tid = threadIdx.x;
    const int wid = tid >> 5;
    const int lane = tid & 31;
    const int g = lane >> 2;
    const int tig = lane & 3;
    const int warp_m = (wid & 3) * 32;
    const int warp_n = (wid >> 2) * 64;
    const int row0 = bx * 128;
    const int n0 = blockIdx.y * 128;
    const __half* Bt = B + (size_t)n0 * K;
    const __half* Ah = (const __half*)Av;
    const float* Af = (const float*)Av;

    float c[2][8][4];
#pragma unroll
    for (int mt = 0; mt < 2; mt++)
#pragma unroll
        for (int nt = 0; nt < 8; nt++)
#pragma unroll
            for (int q = 0; q < 4; q++) c[mt][nt][q] = 0.f;

    const int NIT = K >> 5;    // BK = 32

    auto load_stage = [&](int s, int k0) {
        uint32_t sb = smbase + s * STAGE;
        if (AF32) {
#pragma unroll
            for (int i = 0; i < 4; i++) {
                int cid = tid + i * 256;
                int m = cid >> 3, kc = (cid & 7) << 2;
                const float* src = Af + (size_t)(row0 + m) * K + k0 + kc;
                uint32_t dst = sb + (m * 36 + kc) * 4;
                unsigned sz = (row0 + m < M) ? 16u : 0u;
                asm volatile("cp.async.cg.shared.global [%0], [%1], 16, %2;"
                             :: "r"(dst), "l"(src), "r"(sz));
            }
        } else {
#pragma unroll
            for (int i = 0; i < 2; i++) {
                int cid = tid + i * 256;
                int m = cid >> 2, kc = (cid & 3) << 3;
                const __half* src = Ah + (size_t)(row0 + m) * K + k0 + kc;
                uint32_t dst = sb + (m * 40 + kc) * 2;
                unsigned sz = (row0 + m < M) ? 16u : 0u;
                asm volatile("cp.async.cg.shared.global [%0], [%1], 16, %2;"
                             :: "r"(dst), "l"(src), "r"(sz));
            }
        }
#pragma unroll
        for (int i = 0; i < 2; i++) {
            int cid = tid + i * 256;
            int nn = cid >> 2, kc = (cid & 3) << 3;
            const __half* src = Bt + (size_t)nn * K + k0 + kc;
            uint32_t dst = sb + A_BYTES + (nn * 40 + kc) * 2;
            asm volatile("cp.async.cg.shared.global [%0], [%1], 16;"
                         :: "r"(dst), "l"(src));
        }
        asm volatile("cp.async.commit_group;");
    };

    load_stage(0, 0);

    for (int it = 0; it < NIT; it++) {
        int s = it & 1;
        if (it + 1 < NIT) {
            load_stage(s ^ 1, (it + 1) << 5);
            asm volatile("cp.async.wait_group 1;");
        } else {
            asm volatile("cp.async.wait_group 0;");
        }
        __syncthreads();

        char* sbp = smem + s * STAGE;
#pragma unroll
        for (int ks = 0; ks < 2; ks++) {
            const int kb = ks << 4;
            uint32_t a[2][4];
#pragma unroll
            for (int mt = 0; mt < 2; mt++) {
                int mr = warp_m + mt * 16 + g;
                if (AF32) {
                    const float* A32 = (const float*)sbp;
                    float2 f0 = *(const float2*)&A32[mr * 36 + kb + 2 * tig];
                    float2 f1 = *(const float2*)&A32[(mr + 8) * 36 + kb + 2 * tig];
                    float2 f2 = *(const float2*)&A32[mr * 36 + kb + 2 * tig + 8];
                    float2 f3 = *(const float2*)&A32[(mr + 8) * 36 + kb + 2 * tig + 8];
                    a[mt][0] = packh2(f0.x, f0.y);
                    a[mt][1] = packh2(f1.x, f1.y);
                    a[mt][2] = packh2(f2.x, f2.y);
                    a[mt][3] = packh2(f3.x, f3.y);
                } else {
                    const __half* A16 = (const __half*)sbp;
                    a[mt][0] = *(const uint32_t*)&A16[mr * 40 + kb + 2 * tig];
                    a[mt][1] = *(const uint32_t*)&A16[(mr + 8) * 40 + kb + 2 * tig];
                    a[mt][2] = *(const uint32_t*)&A16[mr * 40 + kb + 2 * tig + 8];
                    a[mt][3] = *(const uint32_t*)&A16[(mr + 8) * 40 + kb + 2 * tig + 8];
                }
            }
            const __half* Bs = (const __half*)(sbp + A_BYTES);
            uint32_t b[8][2];
#pragma unroll
            for (int nt = 0; nt < 8; nt++) {
                int nc = warp_n + nt * 8 + g;
                b[nt][0] = *(const uint32_t*)&Bs[nc * 40 + kb + 2 * tig];
                b[nt][1] = *(const uint32_t*)&Bs[nc * 40 + kb + 2 * tig + 8];
            }
#pragma unroll
            for (int mt = 0; mt < 2; mt++)
#pragma unroll
                for (int nt = 0; nt < 8; nt++) {
                    asm volatile(
                        "mma.sync.aligned.m16n8k16.row.col.f32.f16.f16.f32 "
                        "{%0,%1,%2,%3}, {%4,%5,%6,%7}, {%8,%9}, {%0,%1,%2,%3};"
                        : "+f"(c[mt][nt][0]), "+f"(c[mt][nt][1]),
                          "+f"(c[mt][nt][2]), "+f"(c[mt][nt][3])
                        : "r"(a[mt][0]), "r"(a[mt][1]), "r"(a[mt][2]), "r"(a[mt][3]),
                          "r"(b[nt][0]), "r"(b[nt][1]));
                }
        }
        __syncthreads();
    }

    // ---- epilogue ----
#pragma unroll
    for (int nt = 0; nt < 8; nt++) {
        int col = n0 + warp_n + nt * 8 + tig * 2;
        float b0 = bias[col], b1 = bias[col + 1];
#pragma unroll
        for (int mt = 0; mt < 2; mt++) {
#pragma unroll
            for (int h = 0; h < 2; h++) {
                int row = row0 + warp_m + mt * 16 + g + h * 8;
                if (row < M) {
                    float o0 = alpha * c[mt][nt][h * 2 + 0] + b0;
                    float o1 = alpha * c[mt][nt][h * 2 + 1] + b1;
                    if (EPI == 1) { o0 = fmaxf(o0, 0.f); o1 = fmaxf(o1, 0.f); }
                    if (EPI == 2) {
                        __half2 rv = *(const __half2*)(resid + (size_t)row * ldC + col);
                        float2 rf = __half22float2(rv);
                        o0 += rf.x; o1 += rf.y;
                    }
                    if (OUTF)
                        *(float2*)(Cf + (size_t)row * ldC + col) = make_float2(o0, o1);
                    if (OUTH)
                        *(__half2*)(Ch + (size_t)row * ldC + col) =
                            __floats2half2_rn(o0, o1);
                }
            }
        }
    }
}

// ---------------------------------------------------------------------------
// FC GEMM: K=128 resident-A, internal loop over 4 N-tiles (N=512 total).
// ---------------------------------------------------------------------------
#define FC_A_BYTES (4 * 10240)               // 40960
#define FC_SMEM    (FC_A_BYTES + 2 * 10240)  // 61440

__global__ void __launch_bounds__(256, 2)
mma_fc2(const __half* __restrict__ A1, const __half* __restrict__ A2,
        const __half* __restrict__ B1, const __half* __restrict__ B2,
        const float* __restrict__ bias1, const float* __restrict__ bias2,
        float* __restrict__ Cf1, float* __restrict__ Cf2,
        int M1, int M2, int nblk1) {
    extern __shared__ __align__(16) char smem[];
    const uint32_t smbase = smem_u32(smem);

    const bool second = (int)blockIdx.x >= nblk1;
    const int bx = second ? blockIdx.x - nblk1 : blockIdx.x;
    const int M = second ? M2 : M1;
    const __half* A = second ? A2 : A1;
    const __half* B = second ? B2 : B1;
    const float* bias = second ? bias2 : bias1;
    float* Cf = second ? Cf2 : Cf1;

    const int tid = threadIdx.x;
    const int wid = tid >> 5;
    const int lane = tid & 31;
    const int g = lane >> 2;
    const int tig = lane & 3;
    const int warp_m = (wid & 3) * 32;
    const int warp_n = (wid >> 2) * 64;
    const int row0 = bx * 128;

#pragma unroll
    for (int chunk = 0; chunk < 4; chunk++) {
#pragma unroll
        for (int i = 0; i < 2; i++) {
            int cid = tid + i * 256;
            int m = cid >> 2, kc = (cid & 3) << 3;
            const __half* src = A + (size_t)(row0 + m) * HID + chunk * 32 + kc;
            uint32_t dst = smbase + chunk * 10240 + (m * 40 + kc) * 2;
            unsigned sz = (row0 + m < M) ? 16u : 0u;
            asm volatile("cp.async.cg.shared.global [%0], [%1], 16, %2;"
                         :: "r"(dst), "l"(src), "r"(sz));
        }
    }
    auto load_b = [&](int gi) {
        int y = gi >> 2, it = gi & 3;
        uint32_t sb = smbase + FC_A_BYTES + (gi & 1) * 10240;
        const __half* Bt = B + (size_t)(y * 128) * HID + it * 32;
#pragma unroll
        for (int i = 0; i < 2; i++) {
            int cid = tid + i * 256;
            int nn = cid >> 2, kc = (cid & 3) << 3;
            const __half* src = Bt + (size_t)nn * HID + kc;
            uint32_t dst = sb + (nn * 40 + kc) * 2;
            asm volatile("cp.async.cg.shared.global [%0], [%1], 16;"
                         :: "r"(dst), "l"(src));
        }
        asm volatile("cp.async.commit_group;");
    };

    load_b(0);

    float c[2][8][4];
#pragma unroll
    for (int mt = 0; mt < 2; mt++)
#pragma unroll
        for (int nt = 0; nt < 8; nt++)
#pragma unroll
            for (int q = 0; q < 4; q++) c[mt][nt][q] = 0.f;

    for (int gi = 0; gi < 16; gi++) {
        if (gi + 1 < 16) {
            load_b(gi + 1);
            asm volatile("cp.async.wait_group 1;");
        } else {
            asm volatile("cp.async.wait_group 0;");
        }
        __syncthreads();

        const __half* As = (const __half*)(smem + (gi & 3) * 10240);
        const __half* Bs = (const __half*)(smem + FC_A_BYTES + (gi & 1) * 10240);
#pragma unroll
        for (int ks = 0; ks < 2; ks++) {
            const int kb = ks << 4;
            uint32_t a[2][4];
#pragma unroll
            for (int mt = 0; mt < 2; mt++) {
                int mr = warp_m + mt * 16 + g;
                a[mt][0] = *(const uint32_t*)&As[mr * 40 + kb + 2 * tig];
                a[mt][1] = *(const uint32_t*)&As[(mr + 8) * 40 + kb + 2 * tig];
                a[mt][2] = *(const uint32_t*)&As[mr * 40 + kb + 2 * tig + 8];
                a[mt][3] = *(const uint32_t*)&As[(mr + 8) * 40 + kb + 2 * tig + 8];
            }
            uint32_t b[8][2];
#pragma unroll
            for (int nt = 0; nt < 8; nt++) {
                int nc = warp_n + nt * 8 + g;
                b[nt][0] = *(const uint32_t*)&Bs[nc * 40 + kb + 2 * tig];
                b[nt][1] = *(const uint32_t*)&Bs[nc * 40 + kb + 2 * tig + 8];
            }
#pragma unroll
            for (int mt = 0; mt < 2; mt++)
#pragma unroll
                for (int nt = 0; nt < 8; nt++) {
                    asm volatile(
                        "mma.sync.aligned.m16n8k16.row.col.f32.f16.f16.f32 "
                        "{%0,%1,%2,%3}, {%4,%5,%6,%7}, {%8,%9}, {%0,%1,%2,%3};"
                        : "+f"(c[mt][nt][0]), "+f"(c[mt][nt][1]),
                          "+f"(c[mt][nt][2]), "+f"(c[mt][nt][3])
                        : "r"(a[mt][0]), "r"(a[mt][1]), "r"(a[mt][2]), "r"(a[mt][3]),
                          "r"(b[nt][0]), "r"(b[nt][1]));
                }
        }
        __syncthreads();

        if ((gi & 3) == 3) {
            int y = gi >> 2;
#pragma unroll
            for (int nt = 0; nt < 8; nt++) {
                int col = y * 128 + warp_n + nt * 8 + tig * 2;
                float b0 = bias[col], b1 = bias[col + 1];
#pragma unroll
                for (int mt = 0; mt < 2; mt++) {
#pragma unroll
                    for (int h = 0; h < 2; h++) {
                        int row = row0 + warp_m + mt * 16 + g + h * 8;
                        if (row < M) {
                            float o0 = c[mt][nt][h * 2 + 0] + b0;
                            float o1 = c[mt][nt][h * 2 + 1] + b1;
                            *(float2*)(Cf + (size_t)row * RAW + col) =
                                make_float2(o0, o1);
                        }
                    }
                }
            }
#pragma unroll
            for (int mt = 0; mt < 2; mt++)
#pragma unroll
                for (int nt = 0; nt < 8; nt++)
#pragma unroll
                    for (int q = 0; q < 4; q++) c[mt][nt][q] = 0.f;
        }
    }
}

#define SMEM_H  (2 * (128 * 40 * 2 + 128 * 40 * 2))           // 40960
#define SMEM_F  (2 * (128 * 36 * 4 + 128 * 40 * 2))           // 57344

// ---------------------------------------------------------------------------
// Host launch
// ---------------------------------------------------------------------------
extern "C" void kernel_launch(void* const* d_in, const int* in_sizes, int n_in,
                              void* d_out, int out_size) {
    const float* frame = (const float*)d_in[0];
    const float* fe    = (const float*)d_in[1];
    const int* s_ff = (const int*)d_in[2];  const int* d_ff = (const int*)d_in[3];
    const int* s_fE = (const int*)d_in[4];  const int* d_fE = (const int*)d_in[5];  // frfe
    const int* s_ef = (const int*)d_in[6];  const int* d_ef = (const int*)d_in[7];  // fefr
    const int* s_ee = (const int*)d_in[8];  const int* d_ee = (const int*)d_in[9];
    const float* W_fr_lin = (const float*)d_in[10]; const float* b_fr_lin = (const float*)d_in[11];
    const float* W_fe_lin = (const float*)d_in[12]; const float* b_fe_lin = (const float*)d_in[13];
    const float* W_frfr = (const float*)d_in[14];   const float* b_frfr = (const float*)d_in[15];
    const float* W_frfe = (const float*)d_in[16];   const float* b_frfe = (const float*)d_in[17];
    const float* W_fefr = (const float*)d_in[18];   const float* b_fefr = (const float*)d_in[19];
    const float* W_fefe = (const float*)d_in[20];   const float* b_fefe = (const float*)d_in[21];
    const float* W_fr_fc = (const float*)d_in[22];  const float* b_fr_fc = (const float*)d_in[23];
    const float* W_fe_fc = (const float*)d_in[24];  const float* b_fe_fc = (const float*)d_in[25];

    __half *x_fr16, *x_fe16, *h_fr16, *h_fe16, *h2_fr16, *h2_fe16, *aggF, *aggE;
    __half *WlinF_t, *WlinE_t, *WcatF_t, *WcatE_t, *WfcF_t, *WfcE_t;
    float *deg, *bias_gF, *bias_gE;
    int *ideg, *csr_ff, *csr_ef, *csr_fE, *csr_ee;
    int *row_ff, *cur_ff, *row_ef, *cur_ef, *row_fE, *cur_fE, *row_ee, *cur_ee;
    int *part, *bsum;
    cudaGetSymbolAddress((void**)&x_fr16, g_x_fr16);
    cudaGetSymbolAddress((void**)&x_fe16, g_x_fe16);
    cudaGetSymbolAddress((void**)&h_fr16, g_h_fr16);
    cudaGetSymbolAddress((void**)&h_fe16, g_h_fe16);
    cudaGetSymbolAddress((void**)&h2_fr16, g_h2_fr16);
    cudaGetSymbolAddress((void**)&h2_fe16, g_h2_fe16);
    cudaGetSymbolAddress((void**)&aggF, g_aggF);
    cudaGetSymbolAddress((void**)&aggE, g_aggE);
    cudaGetSymbolAddress((void**)&ideg, g_ideg);
    cudaGetSymbolAddress((void**)&deg, g_deg);
    cudaGetSymbolAddress((void**)&WlinF_t, g_WlinF_t);
    cudaGetSymbolAddress((void**)&WlinE_t, g_WlinE_t);
    cudaGetSymbolAddress((void**)&WcatF_t, g_WcatF_t);
    cudaGetSymbolAddress((void**)&WcatE_t, g_WcatE_t);
    cudaGetSymbolAddress((void**)&WfcF_t, g_WfcF_t);
    cudaGetSymbolAddress((void**)&WfcE_t, g_WfcE_t);
    cudaGetSymbolAddress((void**)&bias_gF, g_bias_gF);
    cudaGetSymbolAddress((void**)&bias_gE, g_bias_gE);
    cudaGetSymbolAddress((void**)&csr_ff, g_csr_ff);
    cudaGetSymbolAddress((void**)&csr_ef, g_csr_ef);
    cudaGetSymbolAddress((void**)&csr_fE, g_csr_fE);
    cudaGetSymbolAddress((void**)&csr_ee, g_csr_ee);
    cudaGetSymbolAddress((void**)&row_ff, g_row_ff);
    cudaGetSymbolAddress((void**)&cur_ff, g_cur_ff);
    cudaGetSymbolAddress((void**)&row_ef, g_row_ef);
    cudaGetSymbolAddress((void**)&cur_ef, g_cur_ef);
    cudaGetSymbolAddress((void**)&row_fE, g_row_fE);
    cudaGetSymbolAddress((void**)&cur_fE, g_cur_fE);
    cudaGetSymbolAddress((void**)&row_ee, g_row_ee);
    cudaGetSymbolAddress((void**)&cur_ee, g_cur_ee);
    cudaGetSymbolAddress((void**)&part, g_part);
    cudaGetSymbolAddress((void**)&bsum, g_bsum);

    cudaFuncSetAttribute(mma_gemm2<0, false, true, true>,
                         cudaFuncAttributeMaxDynamicSharedMemorySize, SMEM_F);
    cudaFuncSetAttribute(mma_gemm2<1, false, true, false>,
                         cudaFuncAttributeMaxDynamicSharedMemorySize, SMEM_H);
    cudaFuncSetAttribute(mma_gemm2<2, true, true, false>,
                         cudaFuncAttributeMaxDynamicSharedMemorySize, SMEM_H);
    cudaFuncSetAttribute(mma_fc2,
                         cudaFuncAttributeMaxDynamicSharedMemorySize, FC_SMEM);

    // degree layout
    int* id_out_ff = ideg;
    int* id_in_ff  = ideg + NF;
    int* id_out_fE = ideg + 2 * (size_t)NF;
    int* id_in_ef  = ideg + 3 * (size_t)NF;
    int* id_in_fE  = ideg + 4 * (size_t)NF;
    int* id_out_ef = ideg + 4 * (size_t)NF + NE;
    int* id_out_ee = ideg + 4 * (size_t)NF + 2 * (size_t)NE;
    int* id_in_ee  = ideg + 4 * (size_t)NF + 3 * (size_t)NE;

    float* ns_ff = deg;
    float* nd_ff = deg + NF;
    float* ns_fE = deg + 2 * (size_t)NF;
    float* nd_ef = deg + 3 * (size_t)NF;
    float* nd_fE = deg + 4 * (size_t)NF;
    float* ns_ef = deg + 4 * (size_t)NF + NE;
    float* ns_ee = deg + 4 * (size_t)NF + 2 * (size_t)NE;
    float* nd_ee = deg + 4 * (size_t)NF + 3 * (size_t)NE;

    float* out = (float*)d_out;
    float* o_frh = out;
    float* o_feh = out + (size_t)NF * RAW;
    float* o_hfr = o_feh + (size_t)NE * RAW;
    float* o_hfe = o_hfr + (size_t)NF * HID;

    const int T = 256;
    const size_t degN = (size_t)4 * NF + (size_t)4 * NE;
    const int eb = (NEDGE + T - 1) / T;
    const int nbF = (NF + 255) / 256;   // 391
    const int nbE = (NE + 255) / 256;   // 782

    cudaStream_t s2;
    cudaStreamCreateWithFlags(&s2, cudaStreamNonBlocking);
    cudaEvent_t evFork, evJoin, evX, e1F, e1E, evEnd;
    cudaEventCreateWithFlags(&evFork, cudaEventDisableTiming);
    cudaEventCreateWithFlags(&evJoin, cudaEventDisableTiming);
    cudaEventCreateWithFlags(&evX, cudaEventDisableTiming);
    cudaEventCreateWithFlags(&e1F, cudaEventDisableTiming);
    cudaEventCreateWithFlags(&e1E, cudaEventDisableTiming);
    cudaEventCreateWithFlags(&evEnd, cudaEventDisableTiming);

    // ---- fork ----
    cudaEventRecord(evFork, 0);
    cudaStreamWaitEvent(s2, evFork, 0);

    // side stream: degrees, norms, CSR build
    zero_kernel<<<(unsigned)((degN / 4 + T - 1) / T), T, 0, s2>>>(
        (float*)ideg, degN / 4);
    deg_all_kernel<<<dim3(eb, 4), T, 0, s2>>>(
        s_ff, d_ff, s_ef, d_ef, s_fE, d_fE, s_ee, d_ee,
        id_out_ff, id_in_ff, id_out_ef, id_in_ef,
        id_out_fE, id_in_fE, id_out_ee, id_in_ee, NEDGE);
    norm_kernel<<<(unsigned)((degN + T - 1) / T), T, 0, s2>>>(ideg, deg, (int)degN);
    scan_partial4<<<dim3(nbE, 4), 256, 0, s2>>>(
        id_in_ff, id_in_ef, id_in_fE, id_in_ee, part, bsum, NF, NF, NE, NE);
    scan_bsum4<<<4, 1024, 0, s2>>>(bsum, nbF, nbF, nbE, nbE);
    scan_add4<<<dim3(nbE, 4), 256, 0, s2>>>(part, bsum,
                                            row_ff, cur_ff, row_ef, cur_ef,
                                            row_fE, cur_fE, row_ee, cur_ee,
                                            NF, NF, NE, NE);
    fill4<<<dim3(eb, 4), T, 0, s2>>>(s_ff, d_ff, s_ef, d_ef, s_fE, d_fE, s_ee, d_ee,
                                     cur_ff, csr_ff, cur_ef, csr_ef,
                                     cur_fE, csr_fE, cur_ee, csr_ee, NEDGE);
    cudaEventRecord(evJoin, s2);

    // main stream: weight prep + input linears
    wprep_kernel<<<(295168 + T - 1) / T, T>>>(
        W_fr_lin, W_fe_lin, W_frfr, W_fefr, W_frfe, W_fefe, W_fr_fc, W_fe_fc,
        b_frfr, b_fefr, b_frfe, b_fefe,
        WlinF_t, WlinE_t, WcatF_t, WcatE_t, WfcF_t, WfcE_t, bias_gF, bias_gE);

    const int gFx = (NF + 127) / 128;   // 782
    const int gEx = (NE + 127) / 128;   // 1563
    const int gAll = gFx + gEx;         // 2345
    const unsigned gwF = ((unsigned)NF * 32 + T - 1) / T;
    const unsigned gwE = ((unsigned)NE * 32 + T - 1) / T;

    mma_gemm2<0, false, true, true><<<dim3(gAll, 1), 256, SMEM_F>>>(
        frame, fe, WlinF_t, WlinE_t, b_fr_lin, b_fe_lin, nullptr, nullptr,
        nullptr, nullptr, x_fr16, x_fe16, NF, NE, gFx, RAW, HID, 1.f);
    cudaStreamWaitEvent(0, evJoin, 0);       // CSR ready
    cudaEventRecord(evX, 0);                 // x + CSR ready
    cudaStreamWaitEvent(s2, evX, 0);

    // ==== layer 1: F-chain on main, E-chain on s2 ====
    gather_all<<<gwF, T>>>(x_fr16, x_fe16,
                           csr_ff, row_ff, id_in_ff, ns_ff, nd_ff,
                           csr_ef, row_ef, id_in_ef, ns_ef, nd_ef,
                           csr_fE, row_fE, id_in_fE, ns_fE, nd_fE,
                           csr_ee, row_ee, id_in_ee, ns_ee, nd_ee,
                           aggF, aggE, 0, NF);
    mma_gemm2<1, false, true, false><<<dim3(gFx, 1), 256, SMEM_H>>>(
        aggF, nullptr, WcatF_t, nullptr, bias_gF, nullptr, nullptr, nullptr,
        nullptr, nullptr, h_fr16, nullptr, NF, 0, gFx, 256, HID, 0.5f);
    cudaEventRecord(e1F, 0);

    gather_all<<<gwE, T, 0, s2>>>(x_fr16, x_fe16,
                                  csr_ff, row_ff, id_in_ff, ns_ff, nd_ff,
                                  csr_ef, row_ef, id_in_ef, ns_ef, nd_ef,
                                  csr_fE, row_fE, id_in_fE, ns_fE, nd_fE,
                                  csr_ee, row_ee, id_in_ee, ns_ee, nd_ee,
                                  aggF, aggE, NF, NE);
    mma_gemm2<1, false, true, false><<<dim3(gEx, 1), 256, SMEM_H, s2>>>(
        aggE, nullptr, WcatE_t, nullptr, bias_gE, nullptr, nullptr, nullptr,
        nullptr, nullptr, h_fe16, nullptr, NE, 0, gEx, 256, HID, 0.5f);
    cudaEventRecord(e1E, s2);

    // ==== layer 2 ====
    cudaStreamWaitEvent(0, e1E, 0);          // F gather needs h_fe too
    gather_all<<<gwF, T>>>(h_fr16, h_fe16,
                           csr_ff, row_ff, id_in_ff, ns_ff, nd_ff,
                           csr_ef, row_ef, id_in_ef, ns_ef, nd_ef,
                           csr_fE, row_fE, id_in_fE, ns_fE, nd_fE,
                           csr_ee, row_ee, id_in_ee, ns_ee, nd_ee,
                           aggF, aggE, 0, NF);
    mma_gemm2<2, true, true, false><<<dim3(gFx, 1), 256, SMEM_H>>>(
        aggF, nullptr, WcatF_t, nullptr, bias_gF, nullptr, x_fr16, nullptr,
        o_hfr, nullptr, h2_fr16, nullptr, NF, 0, gFx, 256, HID, 0.5f);
    // FC for F right away on main (needs only h2_fr)
    mma_fc2<<<dim3(gFx, 1), 256, FC_SMEM>>>(
        h2_fr16, nullptr, WfcF_t, nullptr, b_fr_fc, nullptr,
        o_frh, nullptr, NF, 0, gFx);

    cudaStreamWaitEvent(s2, e1F, 0);         // E gather needs h_fr too
    gather_all<<<gwE, T, 0, s2>>>(h_fr16, h_fe16,
                                  csr_ff, row_ff, id_in_ff, ns_ff, nd_ff,
                                  csr_ef, row_ef, id_in_ef, ns_ef, nd_ef,
                                  csr_fE, row_fE, id_in_fE, ns_fE, nd_fE,
                                  csr_ee, row_ee, id_in_ee, ns_ee, nd_ee,
                                  aggF, aggE, NF, NE);
    mma_gemm2<2, true, true, false><<<dim3(gEx, 1), 256, SMEM_H, s2>>>(
        aggE, nullptr, WcatE_t, nullptr, bias_gE, nullptr, x_fe16, nullptr,
        o_hfe, nullptr, h2_fe16, nullptr, NE, 0, gEx, 256, HID, 0.5f);
    mma_fc2<<<dim3(gEx, 1), 256, FC_SMEM, s2>>>(
        h2_fe16, nullptr, WfcE_t, nullptr, b_fe_fc, nullptr,
        o_feh, nullptr, NE, 0, gEx);
    cudaEventRecord(evEnd, s2);
    cudaStreamWaitEvent(0, evEnd, 0);        // join everything back
}